// round 1
// baseline (speedup 1.0000x reference)
#include <cuda_runtime.h>
#include <math.h>

// Problem constants (fixed shapes from setup_inputs)
#define Bb 4
#define Gg 128
#define Nn 2048
#define Pp 4
#define Ff 64
#define BP 16           // B*P
#define ZTOL 1e-9f

// Scratch (device globals; no runtime allocation allowed)
__device__ __align__(16) float  g_Wx[BP * Nn * Ff];   // [bp][n][f], 8MB
__device__ float  g_s1[BP * Nn];
__device__ float  g_s2[BP * Nn];
__device__ float2 g_s2c[BP * Nn];                     // (s2, 1/D)
__device__ int    g_cnt2[32 * Nn];                    // per (mchunk, col) nnz counts
__device__ int    g_colptr[Nn + 1];
__device__ int    g_rowidx[Nn * Nn];                  // CSC rows (worst case dense)
__device__ float  g_vals[Nn * Nn];                    // CSC values

// ---------------------------------------------------------------------------
// K1: Wx[bp][n][f] = sum_g W[p][f][g] * x[b][g][n]; also s1,s2 projections.
// grid (8 nchunks, P, B), 256 threads. Each thread owns one n, 64 f-accs.
// ---------------------------------------------------------------------------
__global__ void k1_wx(const float* __restrict__ x, const float* __restrict__ a,
                      const float* __restrict__ W) {
    const int b = blockIdx.z, p = blockIdx.y;
    const int n = blockIdx.x * 256 + threadIdx.x;

    __shared__ __align__(16) float Ws[Gg * Ff];  // [g][f]
    __shared__ float as[2 * Ff];

    for (int i = threadIdx.x; i < Gg * Ff; i += 256) {
        int f = i >> 7, g = i & 127;                 // i = f*128+g
        Ws[g * Ff + f] = W[(p * Ff + f) * Gg + g];   // W[p][0][f][g]
    }
    if (threadIdx.x < 2 * Ff) as[threadIdx.x] = a[p * 2 * Ff + threadIdx.x];
    __syncthreads();

    float4 acc[16];
#pragma unroll
    for (int i = 0; i < 16; i++) acc[i] = make_float4(0.f, 0.f, 0.f, 0.f);

    const float* xb = x + ((size_t)b * Gg) * Nn + n;
    const float4* Ws4 = (const float4*)Ws;

    for (int g = 0; g < Gg; g++) {
        float xv = xb[(size_t)g * Nn];
#pragma unroll
        for (int i = 0; i < 16; i++) {
            float4 w = Ws4[g * 16 + i];
            acc[i].x += w.x * xv; acc[i].y += w.y * xv;
            acc[i].z += w.z * xv; acc[i].w += w.w * xv;
        }
    }

    const int bp = b * Pp + p;
    float4* dst = (float4*)(g_Wx + ((size_t)(bp * Nn + n)) * Ff);
    float s1 = 0.f, s2 = 0.f;
#pragma unroll
    for (int i = 0; i < 16; i++) {
        dst[i] = acc[i];
        s1 += as[4*i+0] * acc[i].x + as[4*i+1] * acc[i].y
            + as[4*i+2] * acc[i].z + as[4*i+3] * acc[i].w;
        s2 += as[Ff+4*i+0] * acc[i].x + as[Ff+4*i+1] * acc[i].y
            + as[Ff+4*i+2] * acc[i].z + as[Ff+4*i+3] * acc[i].w;
    }
    g_s1[bp * Nn + n] = s1;
    g_s2[bp * Nn + n] = s2;
}

// ---------------------------------------------------------------------------
// K2: per (bp, m) softmax normalizer over masked entries of row m.
// mask(m,n) = |S[m,n] + (n==m)| > ztol. Scores are O(1) -> no max shift needed.
// grid Nn blocks (one per m), 256 threads.
// ---------------------------------------------------------------------------
__global__ void k2_rowstats(const float* __restrict__ S) {
    const int m = blockIdx.x;
    const int tid = threadIdx.x;

    __shared__ float s2s[BP];
    __shared__ float red[8][BP];
    if (tid < BP) s2s[tid] = g_s2[tid * Nn + m];
    __syncthreads();

    float D[BP];
#pragma unroll
    for (int bp = 0; bp < BP; bp++) D[bp] = 0.f;

    for (int n = tid; n < Nn; n += 256) {
        float sv = S[(size_t)m * Nn + n];
        float adj = sv + (n == m ? 1.f : 0.f);
        if (fabsf(adj) > ZTOL) {
#pragma unroll
            for (int bp = 0; bp < BP; bp++) {
                float t = s2s[bp] + g_s1[bp * Nn + n];
                t = fmaxf(t, 0.2f * t);          // leaky relu
                D[bp] += __expf(t);
            }
        }
    }

#pragma unroll
    for (int bp = 0; bp < BP; bp++) {
#pragma unroll
        for (int off = 16; off; off >>= 1)
            D[bp] += __shfl_down_sync(0xffffffffu, D[bp], off);
    }
    const int w = tid >> 5, l = tid & 31;
    if (l == 0) {
#pragma unroll
        for (int bp = 0; bp < BP; bp++) red[w][bp] = D[bp];
    }
    __syncthreads();
    if (tid < BP) {
        float d = 0.f;
#pragma unroll
        for (int ww = 0; ww < 8; ww++) d += red[ww][tid];
        float c = (d > 0.f) ? 1.f / d : 0.f;
        g_s2c[tid * Nn + m] = make_float2(s2s[tid], c);
    }
}

// ---------------------------------------------------------------------------
// K3: deterministic CSC of S (no diagonal add here: y uses raw S).
// ---------------------------------------------------------------------------
__global__ void k3_count(const float* __restrict__ S) {
    const int n = blockIdx.x * 256 + threadIdx.x;
    const int mc = blockIdx.y;
    int c = 0;
    const int m0 = mc * 64;
    for (int mm = 0; mm < 64; mm++) {
        float sv = S[(size_t)(m0 + mm) * Nn + n];
        if (fabsf(sv) > ZTOL) c++;
    }
    g_cnt2[mc * Nn + n] = c;
}

__global__ void k3_scan() {  // single block, 1024 threads, scan 2048 totals
    __shared__ int s[Nn];
    const int tid = threadIdx.x;
    const int n0 = tid, n1 = tid + 1024;
    int tot0 = 0, tot1 = 0;
    for (int mc = 0; mc < 32; mc++) {
        tot0 += g_cnt2[mc * Nn + n0];
        tot1 += g_cnt2[mc * Nn + n1];
    }
    s[n0] = tot0; s[n1] = tot1;
    __syncthreads();
    for (int off = 1; off < Nn; off <<= 1) {
        int a0 = (n0 >= off) ? s[n0 - off] : 0;
        int a1 = (n1 >= off) ? s[n1 - off] : 0;
        __syncthreads();
        s[n0] += a0; s[n1] += a1;
        __syncthreads();
    }
    g_colptr[n0] = s[n0] - tot0;         // exclusive
    g_colptr[n1] = s[n1] - tot1;
    if (tid == 1023) g_colptr[Nn] = s[Nn - 1];
}

__global__ void k3_fill(const float* __restrict__ S) {
    const int n = blockIdx.x * 256 + threadIdx.x;
    const int mc = blockIdx.y;
    int off = g_colptr[n];
    for (int j = 0; j < mc; j++) off += g_cnt2[j * Nn + n];
    const int m0 = mc * 64;
    for (int mm = 0; mm < 64; mm++) {
        int m = m0 + mm;
        float sv = S[(size_t)m * Nn + n];
        if (fabsf(sv) > ZTOL) { g_rowidx[off] = m; g_vals[off] = sv; off++; }
    }
}

// ---------------------------------------------------------------------------
// K4: y[bp][f][n] = relu( sum_{m in col(n)} S[m,n]*exp(leaky(s2[m]+s1[n]))/D[m]
//                        * Wx[bp][m][f] ).
// grid Nn blocks (one per column n), 512 threads = 16 warps (warp = bp).
// Each lane owns f = 2*lane, 2*lane+1 -> Wx reads are 256B coalesced per warp.
// ---------------------------------------------------------------------------
__global__ void k4_out(float* __restrict__ out) {
    const int n = blockIdx.x;
    const int warp = threadIdx.x >> 5;   // bp
    const int lane = threadIdx.x & 31;

    const int start = g_colptr[n], end = g_colptr[n + 1];
    const float s1n = g_s1[warp * Nn + n];
    float acc0 = 0.f, acc1 = 0.f;

#pragma unroll 4
    for (int i = start; i < end; i++) {
        int m = g_rowidx[i];
        float sval = g_vals[i];
        float2 sc = g_s2c[warp * Nn + m];
        float t = sc.x + s1n;
        t = fmaxf(t, 0.2f * t);
        float wgt = sval * __expf(t) * sc.y;
        float2 wx = *(const float2*)(g_Wx + ((size_t)(warp * Nn + m)) * Ff + 2 * lane);
        acc0 += wgt * wx.x;
        acc1 += wgt * wx.y;
    }

    const int b = warp >> 2, p = warp & 3;
    const size_t base = ((size_t)b * (Pp * Ff) + p * Ff) * Nn + n;
    out[base + (size_t)(2 * lane + 0) * Nn] = fmaxf(acc0, 0.f);
    out[base + (size_t)(2 * lane + 1) * Nn] = fmaxf(acc1, 0.f);
}

// ---------------------------------------------------------------------------
extern "C" void kernel_launch(void* const* d_in, const int* in_sizes, int n_in,
                              void* d_out, int out_size) {
    const float* x = (const float*)d_in[0];  // (4,128,2048)
    const float* a = (const float*)d_in[1];  // (4,1,128)
    const float* W = (const float*)d_in[2];  // (4,1,64,128)
    const float* S = (const float*)d_in[3];  // (1,2048,2048)
    float* out = (float*)d_out;              // (4,256,2048)

    k1_wx<<<dim3(8, Pp, Bb), 256>>>(x, a, W);
    k3_count<<<dim3(8, 32), 256>>>(S);
    k3_scan<<<1, 1024>>>();
    k3_fill<<<dim3(8, 32), 256>>>(S);
    k2_rowstats<<<Nn, 256>>>(S);
    k4_out<<<Nn, 512>>>(out);
}